// round 8
// baseline (speedup 1.0000x reference)
#include <cuda_runtime.h>

// Batched per-object 3-layer MLP — 3 sequential kernels, zero atomics/fences.
// R8: K1 CTAs enlarged to 64 rows (32 KB W1 slab, matching K2's slab size)
// to amortize per-CTA overhead; loop body is the proven R7 batch-4 + deferred
// warp_sum8 structure, run twice per warp.
//
//   K1: y1 = W1 @ x + b1                          (256 MB stream, grid 8192)
//   K2: 32 rows of y2 per CTA; fold W3 dot; one plain store of the partial
//   K3: out[o] = sigmoid(sum_c g_part[c][o] + b3) (64 KB)

#define N_OBJ_  2048
#define IN_DIM_ 128
#define MID_    256

__device__ float g_y1[N_OBJ_ * MID_];
__device__ float g_part[8 * N_OBJ_];   // [chunk][object]

__device__ __forceinline__ float dot4(float4 a, float4 b) {
    return fmaf(a.x, b.x, fmaf(a.y, b.y, fmaf(a.z, b.z, a.w * b.w)));
}

__device__ __forceinline__ float sigmoidf_(float t) {
    return 1.0f / (1.0f + __expf(-t));
}

// Butterfly-reduce 8 independent values across the warp (interleaved chains).
__device__ __forceinline__ void warp_sum8(float (&p)[8]) {
#pragma unroll
    for (int off = 16; off > 0; off >>= 1) {
#pragma unroll
        for (int j = 0; j < 8; ++j)
            p[j] += __shfl_xor_sync(0xffffffffu, p[j], off);
    }
}

// ---- K1: 64 rows of y1 per CTA (4 warps x 16 rows, two 8-row passes) ----
__global__ __launch_bounds__(128, 12)
void k1_fc1(const float* __restrict__ x,
            const float* __restrict__ W1,
            const float* __restrict__ b1)
{
    const int o     = blockIdx.x >> 2;       // 4 chunks of 64 rows per object
    const int chunk = blockIdx.x & 3;
    const int warp  = threadIdx.x >> 5;
    const int lane  = threadIdx.x & 31;

    const float4 xv =
        reinterpret_cast<const float4*>(x + (size_t)o * IN_DIM_)[lane];

#pragma unroll
    for (int pass = 0; pass < 2; ++pass) {
        const int row0 = chunk * 64 + warp * 16 + pass * 8;
        // row stride = 128 floats = 32 float4
        const float4* Wr = reinterpret_cast<const float4*>(
                               W1 + (size_t)o * MID_ * IN_DIM_ +
                               (size_t)row0 * IN_DIM_) + lane;

        float part[8];
#pragma unroll
        for (int b = 0; b < 2; ++b) {
            // 4 independent LDG.128 per batch
            const float4 w0 = Wr[(b * 4 + 0) * 32];
            const float4 w1 = Wr[(b * 4 + 1) * 32];
            const float4 w2 = Wr[(b * 4 + 2) * 32];
            const float4 w3 = Wr[(b * 4 + 3) * 32];
            part[b * 4 + 0] = dot4(w0, xv);
            part[b * 4 + 1] = dot4(w1, xv);
            part[b * 4 + 2] = dot4(w2, xv);
            part[b * 4 + 3] = dot4(w3, xv);
        }

        warp_sum8(part);

        if (lane == 0) {
            const float* b1o = b1 + o * MID_ + row0;
            float* y1o = g_y1 + o * MID_ + row0;
#pragma unroll
            for (int j = 0; j < 8; ++j)
                y1o[j] = part[j] + b1o[j];
        }
    }
}

// ---- K2: 32 rows of y2 per CTA + W3 partial; ONE plain store ----
__global__ __launch_bounds__(128, 12)
void k2_fc2(const float* __restrict__ W2,
            const float* __restrict__ b2,
            const float* __restrict__ W3)
{
    const int o     = blockIdx.x >> 3;
    const int chunk = blockIdx.x & 7;
    const int warp  = threadIdx.x >> 5;
    const int lane  = threadIdx.x & 31;

    const float4* y1v = reinterpret_cast<const float4*>(g_y1 + o * MID_);
    const float4 ya = y1v[lane];
    const float4 yb = y1v[32 + lane];

    const int row0 = chunk * 32 + warp * 8;
    // row stride = 256 floats = 64 float4
    const float4* Wr = reinterpret_cast<const float4*>(
                           W2 + (size_t)o * MID_ * MID_ +
                           (size_t)row0 * MID_) + lane;

    float part[8];
#pragma unroll
    for (int b = 0; b < 4; ++b) {
        // 2 rows per batch -> 4 independent LDG.128
        const float4 a0 = Wr[(2 * b)     * 64];
        const float4 a1 = Wr[(2 * b)     * 64 + 32];
        const float4 c0 = Wr[(2 * b + 1) * 64];
        const float4 c1 = Wr[(2 * b + 1) * 64 + 32];
        part[2 * b]     = fmaf(a0.x, ya.x, fmaf(a0.y, ya.y, fmaf(a0.z, ya.z,
                          fmaf(a0.w, ya.w, dot4(a1, yb)))));
        part[2 * b + 1] = fmaf(c0.x, ya.x, fmaf(c0.y, ya.y, fmaf(c0.z, ya.z,
                          fmaf(c0.w, ya.w, dot4(c1, yb)))));
    }

    warp_sum8(part);

    __shared__ float sp[4];
    if (lane == 0) {
        const float* b2o = b2 + o * MID_ + row0;
        const float* W3o = W3 + o * MID_ + row0;
        float p = 0.0f;
#pragma unroll
        for (int j = 0; j < 8; ++j)
            p = fmaf(W3o[j], sigmoidf_(part[j] + b2o[j]), p);
        sp[warp] = p;
    }
    __syncthreads();   // convergent barrier
    if (threadIdx.x == 0)
        g_part[chunk * N_OBJ_ + o] = sp[0] + sp[1] + sp[2] + sp[3];
}

// ---- K3: thread-per-object reduction + sigmoid ----
__global__ __launch_bounds__(128)
void k3_final(const float* __restrict__ b3, float* __restrict__ out)
{
    const int o = blockIdx.x * 128 + threadIdx.x;
    float s = b3[o];
#pragma unroll
    for (int c = 0; c < 8; ++c)
        s += g_part[c * N_OBJ_ + o];
    out[o] = sigmoidf_(s);
}

extern "C" void kernel_launch(void* const* d_in, const int* in_sizes, int n_in,
                              void* d_out, int out_size)
{
    const float* x  = (const float*)d_in[0];
    const float* W1 = (const float*)d_in[1];
    const float* b1 = (const float*)d_in[2];
    const float* W2 = (const float*)d_in[3];
    const float* b2 = (const float*)d_in[4];
    const float* W3 = (const float*)d_in[5];
    const float* b3 = (const float*)d_in[6];
    float* out = (float*)d_out;

    k1_fc1<<<N_OBJ_ * 4, 128>>>(x, W1, b1);
    k2_fc2<<<N_OBJ_ * 8, 128>>>(W2, b2, W3);
    k3_final<<<N_OBJ_ / 128, 128>>>(b3, out);
}

// round 9
// speedup vs baseline: 1.0082x; 1.0082x over previous
#include <cuda_runtime.h>

// Batched per-object 3-layer MLP — 3 kernels chained with Programmatic
// Dependent Launch (PDL) to overlap each kernel's drain with the next one's
// fill. Streaming bodies identical to the proven R7 configuration.
//
//   K1: y1 = W1 @ x + b1                    (256 MB stream, grid 16384)
//   K2: 32 rows of y2 per CTA + W3 partial  (512 MB stream; prefetches W2
//       pre-gridsync so its loads overlap K1's tail)
//   K3: out[o] = sigmoid(sum partials + b3)

#define N_OBJ_  2048
#define IN_DIM_ 128
#define MID_    256

__device__ float g_y1[N_OBJ_ * MID_];
__device__ float g_part[8 * N_OBJ_];   // [chunk][object]

__device__ __forceinline__ float dot4(float4 a, float4 b) {
    return fmaf(a.x, b.x, fmaf(a.y, b.y, fmaf(a.z, b.z, a.w * b.w)));
}

__device__ __forceinline__ float sigmoidf_(float t) {
    return 1.0f / (1.0f + __expf(-t));
}

__device__ __forceinline__ void warp_sum8(float (&p)[8]) {
#pragma unroll
    for (int off = 16; off > 0; off >>= 1) {
#pragma unroll
        for (int j = 0; j < 8; ++j)
            p[j] += __shfl_xor_sync(0xffffffffu, p[j], off);
    }
}

// ---- K1: 32 rows of y1 per CTA (4 warps x 8 rows) — R7 config ----
__global__ __launch_bounds__(128, 12)
void k1_fc1(const float* __restrict__ x,
            const float* __restrict__ W1,
            const float* __restrict__ b1)
{
    cudaTriggerProgrammaticLaunchCompletion();   // let K2 start launching

    const int o     = blockIdx.x >> 3;
    const int chunk = blockIdx.x & 7;
    const int warp  = threadIdx.x >> 5;
    const int lane  = threadIdx.x & 31;

    const float4 xv =
        reinterpret_cast<const float4*>(x + (size_t)o * IN_DIM_)[lane];
    const int row0 = chunk * 32 + warp * 8;
    const float4* Wr = reinterpret_cast<const float4*>(
                           W1 + (size_t)o * MID_ * IN_DIM_ +
                           (size_t)row0 * IN_DIM_) + lane;

    float part[8];
#pragma unroll
    for (int b = 0; b < 2; ++b) {
        const float4 w0 = Wr[(b * 4 + 0) * 32];
        const float4 w1 = Wr[(b * 4 + 1) * 32];
        const float4 w2 = Wr[(b * 4 + 2) * 32];
        const float4 w3 = Wr[(b * 4 + 3) * 32];
        part[b * 4 + 0] = dot4(w0, xv);
        part[b * 4 + 1] = dot4(w1, xv);
        part[b * 4 + 2] = dot4(w2, xv);
        part[b * 4 + 3] = dot4(w3, xv);
    }

    warp_sum8(part);

    if (lane == 0) {
        const float* b1o = b1 + o * MID_ + row0;
        float* y1o = g_y1 + o * MID_ + row0;
#pragma unroll
        for (int j = 0; j < 8; ++j)
            y1o[j] = part[j] + b1o[j];
    }
}

// ---- K2: 32 rows of y2 per CTA + W3 partial; W2 prefetch pre-gridsync ----
__global__ __launch_bounds__(128, 10)
void k2_fc2(const float* __restrict__ W2,
            const float* __restrict__ b2,
            const float* __restrict__ W3)
{
    cudaTriggerProgrammaticLaunchCompletion();   // let K3 start launching

    const int o     = blockIdx.x >> 3;
    const int chunk = blockIdx.x & 7;
    const int warp  = threadIdx.x >> 5;
    const int lane  = threadIdx.x & 31;

    const int row0 = chunk * 32 + warp * 8;
    const float4* Wr = reinterpret_cast<const float4*>(
                           W2 + (size_t)o * MID_ * MID_ +
                           (size_t)row0 * MID_) + lane;

    // Prefetch rows 0,1 of this warp's slab (pure input — legal pre-sync).
    const float4 p_a0 = Wr[0];
    const float4 p_a1 = Wr[32];
    const float4 p_c0 = Wr[64];
    const float4 p_c1 = Wr[96];

    cudaGridDependencySynchronize();             // wait for K1's writes

    const float4* y1v = reinterpret_cast<const float4*>(g_y1 + o * MID_);
    const float4 ya = y1v[lane];
    const float4 yb = y1v[32 + lane];

    float part[8];
    part[0] = fmaf(p_a0.x, ya.x, fmaf(p_a0.y, ya.y, fmaf(p_a0.z, ya.z,
              fmaf(p_a0.w, ya.w, dot4(p_a1, yb)))));
    part[1] = fmaf(p_c0.x, ya.x, fmaf(p_c0.y, ya.y, fmaf(p_c0.z, ya.z,
              fmaf(p_c0.w, ya.w, dot4(p_c1, yb)))));

#pragma unroll
    for (int b = 1; b < 4; ++b) {
        const float4 a0 = Wr[(2 * b)     * 64];
        const float4 a1 = Wr[(2 * b)     * 64 + 32];
        const float4 c0 = Wr[(2 * b + 1) * 64];
        const float4 c1 = Wr[(2 * b + 1) * 64 + 32];
        part[2 * b]     = fmaf(a0.x, ya.x, fmaf(a0.y, ya.y, fmaf(a0.z, ya.z,
                          fmaf(a0.w, ya.w, dot4(a1, yb)))));
        part[2 * b + 1] = fmaf(c0.x, ya.x, fmaf(c0.y, ya.y, fmaf(c0.z, ya.z,
                          fmaf(c0.w, ya.w, dot4(c1, yb)))));
    }

    warp_sum8(part);

    __shared__ float sp[4];
    if (lane == 0) {
        const float* b2o = b2 + o * MID_ + row0;
        const float* W3o = W3 + o * MID_ + row0;
        float p = 0.0f;
#pragma unroll
        for (int j = 0; j < 8; ++j)
            p = fmaf(W3o[j], sigmoidf_(part[j] + b2o[j]), p);
        sp[warp] = p;
    }
    __syncthreads();   // convergent barrier
    if (threadIdx.x == 0)
        g_part[chunk * N_OBJ_ + o] = sp[0] + sp[1] + sp[2] + sp[3];
}

// ---- K3: thread-per-object reduction + sigmoid ----
__global__ __launch_bounds__(128)
void k3_final(const float* __restrict__ b3, float* __restrict__ out)
{
    cudaGridDependencySynchronize();             // wait for K2's partials

    const int o = blockIdx.x * 128 + threadIdx.x;
    float s = b3[o];
#pragma unroll
    for (int c = 0; c < 8; ++c)
        s += g_part[c * N_OBJ_ + o];
    out[o] = sigmoidf_(s);
}

extern "C" void kernel_launch(void* const* d_in, const int* in_sizes, int n_in,
                              void* d_out, int out_size)
{
    const float* x  = (const float*)d_in[0];
    const float* W1 = (const float*)d_in[1];
    const float* b1 = (const float*)d_in[2];
    const float* W2 = (const float*)d_in[3];
    const float* b2 = (const float*)d_in[4];
    const float* W3 = (const float*)d_in[5];
    const float* b3 = (const float*)d_in[6];
    float* out = (float*)d_out;

    // K1: plain launch
    k1_fc1<<<N_OBJ_ * 8, 128>>>(x, W1, b1);

    // K2, K3: PDL-chained launches
    cudaLaunchAttribute attr[1];
    attr[0].id = cudaLaunchAttributeProgrammaticStreamSerialization;
    attr[0].val.programmaticStreamSerializationAllowed = 1;

    {
        cudaLaunchConfig_t cfg = {};
        cfg.gridDim  = dim3(N_OBJ_ * 8);
        cfg.blockDim = dim3(128);
        cfg.stream   = 0;
        cfg.attrs    = attr;
        cfg.numAttrs = 1;
        cudaLaunchKernelEx(&cfg, k2_fc2, W2, b2, W3);
    }
    {
        cudaLaunchConfig_t cfg = {};
        cfg.gridDim  = dim3(N_OBJ_ / 128);
        cfg.blockDim = dim3(128);
        cfg.stream   = 0;
        cfg.attrs    = attr;
        cfg.numAttrs = 1;
        cudaLaunchKernelEx(&cfg, k3_final, b3, out);
    }
}

// round 10
// speedup vs baseline: 1.0210x; 1.0127x over previous
#include <cuda_runtime.h>

// Batched per-object 3-layer MLP — 3 kernels, PDL-chained.
// R10: K1 = 256-thread CTAs (8 warps x 8 rows, single pass, 64-row slab,
// grid 8192) to halve per-CTA fixed cost without serializing passes.
//
//   K1: y1 = W1 @ x + b1                    (256 MB stream)
//   K2: 32 rows of y2 per CTA + W3 partial  (512 MB stream, W2 prefetch)
//   K3: out[o] = sigmoid(sum partials + b3)

#define N_OBJ_  2048
#define IN_DIM_ 128
#define MID_    256

__device__ float g_y1[N_OBJ_ * MID_];
__device__ float g_part[8 * N_OBJ_];   // [chunk][object]

__device__ __forceinline__ float dot4(float4 a, float4 b) {
    return fmaf(a.x, b.x, fmaf(a.y, b.y, fmaf(a.z, b.z, a.w * b.w)));
}

__device__ __forceinline__ float sigmoidf_(float t) {
    return 1.0f / (1.0f + __expf(-t));
}

__device__ __forceinline__ void warp_sum8(float (&p)[8]) {
#pragma unroll
    for (int off = 16; off > 0; off >>= 1) {
#pragma unroll
        for (int j = 0; j < 8; ++j)
            p[j] += __shfl_xor_sync(0xffffffffu, p[j], off);
    }
}

// ---- K1: 64 rows per CTA, 8 warps x 8 rows, single pass ----
__global__ __launch_bounds__(256, 6)
void k1_fc1(const float* __restrict__ x,
            const float* __restrict__ W1,
            const float* __restrict__ b1)
{
    cudaTriggerProgrammaticLaunchCompletion();

    const int o     = blockIdx.x >> 2;       // 4 chunks of 64 rows
    const int chunk = blockIdx.x & 3;
    const int warp  = threadIdx.x >> 5;
    const int lane  = threadIdx.x & 31;

    const float4 xv =
        reinterpret_cast<const float4*>(x + (size_t)o * IN_DIM_)[lane];
    const int row0 = chunk * 64 + warp * 8;
    // row stride = 128 floats = 32 float4
    const float4* Wr = reinterpret_cast<const float4*>(
                           W1 + (size_t)o * MID_ * IN_DIM_ +
                           (size_t)row0 * IN_DIM_) + lane;

    float part[8];
#pragma unroll
    for (int b = 0; b < 2; ++b) {
        const float4 w0 = Wr[(b * 4 + 0) * 32];
        const float4 w1 = Wr[(b * 4 + 1) * 32];
        const float4 w2 = Wr[(b * 4 + 2) * 32];
        const float4 w3 = Wr[(b * 4 + 3) * 32];
        part[b * 4 + 0] = dot4(w0, xv);
        part[b * 4 + 1] = dot4(w1, xv);
        part[b * 4 + 2] = dot4(w2, xv);
        part[b * 4 + 3] = dot4(w3, xv);
    }

    warp_sum8(part);

    if (lane == 0) {
        const float* b1o = b1 + o * MID_ + row0;
        float* y1o = g_y1 + o * MID_ + row0;
#pragma unroll
        for (int j = 0; j < 8; ++j)
            y1o[j] = part[j] + b1o[j];
    }
}

// ---- K2: 32 rows of y2 per CTA + W3 partial; W2 prefetch pre-gridsync ----
__global__ __launch_bounds__(128, 10)
void k2_fc2(const float* __restrict__ W2,
            const float* __restrict__ b2,
            const float* __restrict__ W3)
{
    cudaTriggerProgrammaticLaunchCompletion();

    const int o     = blockIdx.x >> 3;
    const int chunk = blockIdx.x & 7;
    const int warp  = threadIdx.x >> 5;
    const int lane  = threadIdx.x & 31;

    const int row0 = chunk * 32 + warp * 8;
    const float4* Wr = reinterpret_cast<const float4*>(
                           W2 + (size_t)o * MID_ * MID_ +
                           (size_t)row0 * MID_) + lane;

    // Prefetch rows 0,1 (pure input — legal pre-sync).
    const float4 p_a0 = Wr[0];
    const float4 p_a1 = Wr[32];
    const float4 p_c0 = Wr[64];
    const float4 p_c1 = Wr[96];

    cudaGridDependencySynchronize();

    const float4* y1v = reinterpret_cast<const float4*>(g_y1 + o * MID_);
    const float4 ya = y1v[lane];
    const float4 yb = y1v[32 + lane];

    float part[8];
    part[0] = fmaf(p_a0.x, ya.x, fmaf(p_a0.y, ya.y, fmaf(p_a0.z, ya.z,
              fmaf(p_a0.w, ya.w, dot4(p_a1, yb)))));
    part[1] = fmaf(p_c0.x, ya.x, fmaf(p_c0.y, ya.y, fmaf(p_c0.z, ya.z,
              fmaf(p_c0.w, ya.w, dot4(p_c1, yb)))));

#pragma unroll
    for (int b = 1; b < 4; ++b) {
        const float4 a0 = Wr[(2 * b)     * 64];
        const float4 a1 = Wr[(2 * b)     * 64 + 32];
        const float4 c0 = Wr[(2 * b + 1) * 64];
        const float4 c1 = Wr[(2 * b + 1) * 64 + 32];
        part[2 * b]     = fmaf(a0.x, ya.x, fmaf(a0.y, ya.y, fmaf(a0.z, ya.z,
                          fmaf(a0.w, ya.w, dot4(a1, yb)))));
        part[2 * b + 1] = fmaf(c0.x, ya.x, fmaf(c0.y, ya.y, fmaf(c0.z, ya.z,
                          fmaf(c0.w, ya.w, dot4(c1, yb)))));
    }

    warp_sum8(part);

    __shared__ float sp[4];
    if (lane == 0) {
        const float* b2o = b2 + o * MID_ + row0;
        const float* W3o = W3 + o * MID_ + row0;
        float p = 0.0f;
#pragma unroll
        for (int j = 0; j < 8; ++j)
            p = fmaf(W3o[j], sigmoidf_(part[j] + b2o[j]), p);
        sp[warp] = p;
    }
    __syncthreads();   // convergent barrier
    if (threadIdx.x == 0)
        g_part[chunk * N_OBJ_ + o] = sp[0] + sp[1] + sp[2] + sp[3];
}

// ---- K3: thread-per-object reduction + sigmoid ----
__global__ __launch_bounds__(128)
void k3_final(const float* __restrict__ b3, float* __restrict__ out)
{
    cudaGridDependencySynchronize();

    const int o = blockIdx.x * 128 + threadIdx.x;
    float s = b3[o];
#pragma unroll
    for (int c = 0; c < 8; ++c)
        s += g_part[c * N_OBJ_ + o];
    out[o] = sigmoidf_(s);
}

extern "C" void kernel_launch(void* const* d_in, const int* in_sizes, int n_in,
                              void* d_out, int out_size)
{
    const float* x  = (const float*)d_in[0];
    const float* W1 = (const float*)d_in[1];
    const float* b1 = (const float*)d_in[2];
    const float* W2 = (const float*)d_in[3];
    const float* b2 = (const float*)d_in[4];
    const float* W3 = (const float*)d_in[5];
    const float* b3 = (const float*)d_in[6];
    float* out = (float*)d_out;

    k1_fc1<<<N_OBJ_ * 4, 256>>>(x, W1, b1);

    cudaLaunchAttribute attr[1];
    attr[0].id = cudaLaunchAttributeProgrammaticStreamSerialization;
    attr[0].val.programmaticStreamSerializationAllowed = 1;

    {
        cudaLaunchConfig_t cfg = {};
        cfg.gridDim  = dim3(N_OBJ_ * 8);
        cfg.blockDim = dim3(128);
        cfg.stream   = 0;
        cfg.attrs    = attr;
        cfg.numAttrs = 1;
        cudaLaunchKernelEx(&cfg, k2_fc2, W2, b2, W3);
    }
    {
        cudaLaunchConfig_t cfg = {};
        cfg.gridDim  = dim3(N_OBJ_ / 128);
        cfg.blockDim = dim3(128);
        cfg.stream   = 0;
        cfg.attrs    = attr;
        cfg.numAttrs = 1;
        cudaLaunchKernelEx(&cfg, k3_final, b3, out);
    }
}